// round 14
// baseline (speedup 1.0000x reference)
#include <cuda_runtime.h>
#include <cstdint>
#include <math.h>

// ============================ config ============================
#define NTHREADS 128
#define TILE_M   128          // 4 warps x m=32, 2 CTAs/SM

// fp8 row strides (bytes)
#define WROW_L0  80           // k=64  + pad
#define WROW_MID 144          // k=128 + pad
#define WROW_L4  208          // k=192 + pad
#define ACT_ROW  144
#define ENC_ROW  80

#define HEAD_INV (1.0f/4096.0f)   // head weights pre-scaled by 4096 (e4m3 subnormal floor!)

// g_wscratch word offsets per slot {L0,L1,L2,L3,L4,L5,head}
__device__ __constant__ int SLOT_OFF[7] = {0, 2560, 7168, 11776, 16384, 23040, 27648};
__device__ uint32_t g_wscratch[27936];
__device__ float    g_biasg[6 * 128];

// smem layout (bytes)
#define ENC_OFF    0          // 128 x 80
#define ACT_OFF    10240      // 128 x 144
#define WB0_OFF    28672      // 128 x 208 max (L0, L2, L4, head)
#define WB1_OFF    55296      // 128 x 144     (L1, L3, L5)
#define SBIAS0_OFF 73728
#define SBIAS1_OFF 74240
#define SCREW_OFF  74752      // 128 x 8 f32
#define SMEM_BYTES 78848

// ============================ helpers ============================
__device__ __forceinline__ uint32_t smem_to_u32(const void* p) {
    uint32_t a;
    asm("{ .reg .u64 t; cvta.to.shared.u64 t, %1; cvt.u32.u64 %0, t; }" : "=r"(a) : "l"(p));
    return a;
}

__device__ __forceinline__ void ldmx4(uint32_t& r0, uint32_t& r1, uint32_t& r2, uint32_t& r3, uint32_t addr) {
    asm volatile("ldmatrix.sync.aligned.m8n8.x4.shared.b16 {%0,%1,%2,%3}, [%4];"
        : "=r"(r0), "=r"(r1), "=r"(r2), "=r"(r3) : "r"(addr));
}
__device__ __forceinline__ void ldmx2(uint32_t& r0, uint32_t& r1, uint32_t addr) {
    asm volatile("ldmatrix.sync.aligned.m8n8.x2.shared.b16 {%0,%1}, [%2];"
        : "=r"(r0), "=r"(r1) : "r"(addr));
}

// e4m3 x e4m3 -> f32 accum, m16n8k32
__device__ __forceinline__ void mma8(float (&c)[4], const uint32_t* a, uint32_t b0, uint32_t b1) {
    asm volatile("mma.sync.aligned.m16n8k32.row.col.f32.e4m3.e4m3.f32 "
        "{%0,%1,%2,%3}, {%4,%5,%6,%7}, {%8,%9}, {%0,%1,%2,%3};"
        : "+f"(c[0]), "+f"(c[1]), "+f"(c[2]), "+f"(c[3])
        : "r"(a[0]), "r"(a[1]), "r"(a[2]), "r"(a[3]), "r"(b0), "r"(b1));
}

// cvt two f32 -> packed e4m3x2; PTX requires .b16 destination ("=h")
__device__ __forceinline__ uint32_t cvt_e4m3x2(float hi, float lo) {
    unsigned short d;
    asm("cvt.rn.satfinite.e4m3x2.f32 %0, %1, %2;" : "=h"(d) : "f"(hi), "f"(lo));
    return (uint32_t)d;
}
// pack 4 floats into 4 fp8 bytes (byte0 = f0)
__device__ __forceinline__ uint32_t pack4_fp8(float f0, float f1, float f2, float f3) {
    return cvt_e4m3x2(f1, f0) | (cvt_e4m3x2(f3, f2) << 16);
}
__device__ __forceinline__ void st16(uint32_t addr, uint32_t v) {
    asm volatile("st.shared.b16 [%0], %1;" :: "r"(addr), "h"((unsigned short)v));
}

__device__ __forceinline__ void cp_async16(uint32_t dst, const void* src) {
    asm volatile("cp.async.cg.shared.global [%0], [%1], 16;" :: "r"(dst), "l"(src));
}
#define CP_COMMIT()   asm volatile("cp.async.commit_group;" ::: "memory")
#define CP_WAIT_ALL() asm volatile("cp.async.wait_all;" ::: "memory")

// weight element fetch (k = element index); head scaled by 4096 (e4m3 range)
__device__ __forceinline__ float wfetch(int mode, int n, int k, const float* Wa, const float* Wb) {
    if (mode == 0) return __ldg(Wa + n * 128 + k);
    if (mode == 1) return (k < 53) ? __ldg(Wa + n * 53 + k) : 0.0f;
    if (mode == 2) {
        if (k < 53) return __ldg(Wa + n * 181 + k);
        if (k < 64) return 0.0f;
        return __ldg(Wa + n * 181 + (k - 11));
    }
    if (n < 3) return __ldg(Wa + n * 128 + k) * 4096.0f;
    if (n < 6) return __ldg(Wb + (n - 3) * 128 + k) * 4096.0f;
    return 0.0f;
}

// ============================ prep kernel ============================
__global__ void prep_weights(
    const float* W0, const float* W1, const float* W2, const float* W3,
    const float* W4, const float* W5, const float* Wv, const float* Wr,
    const float* b0, const float* b1, const float* b2, const float* b3,
    const float* b4, const float* b5)
{
    int slot = blockIdx.y;
    int idx = blockIdx.x * 256 + threadIdx.x;
    uint32_t* dst = g_wscratch + SLOT_OFF[slot];

    const float *Wa = nullptr, *Wb = nullptr, *bb = nullptr;
    int mode = 0, rows = 128, wroww = 36, datk = 128;
    switch (slot) {
        case 0: Wa = W0; mode = 1; wroww = 20; datk = 64;  bb = b0; break;
        case 1: Wa = W1; mode = 0; wroww = 36; datk = 128; bb = b1; break;
        case 2: Wa = W2; mode = 0; wroww = 36; datk = 128; bb = b2; break;
        case 3: Wa = W3; mode = 0; wroww = 36; datk = 128; bb = b3; break;
        case 4: Wa = W4; mode = 2; wroww = 52; datk = 192; bb = b4; break;
        case 5: Wa = W5; mode = 0; wroww = 36; datk = 128; bb = b5; break;
        case 6: Wa = Wv; Wb = Wr; mode = 3; rows = 8; wroww = 36; datk = 128; break;
    }
    int words = rows * wroww;
    if (idx < words) {
        int n = idx / wroww;
        int kp = idx - n * wroww;
        uint32_t v = 0;
        if (kp * 4 < datk) {
            int k = kp * 4;
            v = pack4_fp8(wfetch(mode, n, k,     Wa, Wb),
                          wfetch(mode, n, k + 1, Wa, Wb),
                          wfetch(mode, n, k + 2, Wa, Wb),
                          wfetch(mode, n, k + 3, Wa, Wb));
        }
        dst[idx] = v;
    } else if (bb && (idx - words) < 128) {
        g_biasg[slot * 128 + (idx - words)] = __ldg(bb + (idx - words));
    }
}

// ============================ main kernel pieces ============================
__device__ __forceinline__ void stage_async(uint32_t dst, const uint32_t* src, int words4,
                                            const float* bsrc, uint32_t sbias_dst, int t, int nthr) {
    const uint4* s = (const uint4*)src;
    #pragma unroll 4
    for (int i = t; i < words4; i += nthr)
        cp_async16(dst + (uint32_t)i * 16u, s + i);
    if (bsrc && t < 32)
        cp_async16(sbias_dst + (uint32_t)t * 16u, (const uint4*)bsrc + t);
}

// fp8 dense layer: kc-outer / n-tile-pair inner; one ldmx4 covers 2 n-tiles
template<int NCH, int ENCCH, int WROWB>
__device__ __forceinline__ void do_layer8(float (&C)[2][16][4],
    const uint32_t (&Aenc)[2][8], const uint32_t (&Aact)[2][16],
    uint32_t wbase, const float* sbias, int lane)
{
    const int tq2 = (lane & 3) * 2;
    #pragma unroll
    for (int nt = 0; nt < 16; ++nt) {
        float b0 = sbias[nt * 8 + tq2], b1 = sbias[nt * 8 + tq2 + 1];
        C[0][nt][0] = b0; C[0][nt][1] = b1; C[0][nt][2] = b0; C[0][nt][3] = b1;
        C[1][nt][0] = b0; C[1][nt][1] = b1; C[1][nt][2] = b0; C[1][nt][3] = b1;
    }
    // B addressing: lanes 0-7 tile-lo bytes0-15, 8-15 tile-lo bytes16-31,
    //               16-23 tile-hi bytes0-15, 24-31 tile-hi bytes16-31
    const uint32_t baddr = wbase + (uint32_t)((lane & 7) + ((lane >> 4) << 3)) * WROWB
                         + (uint32_t)((lane >> 3) & 1) * 16u;
    #pragma unroll
    for (int kc = 0; kc < NCH; ++kc) {
        const uint32_t* A0 = (kc < ENCCH) ? &Aenc[0][kc * 4] : &Aact[0][(kc - ENCCH) * 4];
        const uint32_t* A1 = (kc < ENCCH) ? &Aenc[1][kc * 4] : &Aact[1][(kc - ENCCH) * 4];
        const uint32_t kaddr = baddr + (uint32_t)kc * 32u;
        #pragma unroll
        for (int j2 = 0; j2 < 8; ++j2) {
            uint32_t r0, r1, r2, r3;
            ldmx4(r0, r1, r2, r3, kaddr + (uint32_t)j2 * (16u * WROWB));
            mma8(C[0][2 * j2],     A0, r0, r1);
            mma8(C[1][2 * j2],     A1, r0, r1);
            mma8(C[0][2 * j2 + 1], A0, r2, r3);
            mma8(C[1][2 * j2 + 1], A1, r2, r3);
        }
    }
}

// relu + cvt fp8 + store to warp-private act rows (no cross-warp hazard)
// m-tile t rows = warpbase + 16*t + {q, q+8}  (16*t, NOT 32*t!)
__device__ __forceinline__ void store_act8(const float (&C)[2][16][4],
    uint32_t actb, int warpbase, int lane)
{
    const int tq = lane & 3, q = lane >> 2;
    #pragma unroll
    for (int t = 0; t < 2; ++t) {
        uint32_t ra = actb + (uint32_t)(warpbase + 16 * t + q) * ACT_ROW + (uint32_t)(2 * tq);
        uint32_t rb = ra + 8u * ACT_ROW;
        #pragma unroll
        for (int j = 0; j < 16; ++j) {
            uint32_t lo = cvt_e4m3x2(fmaxf(C[t][j][1], 0.f), fmaxf(C[t][j][0], 0.f));
            uint32_t hi = cvt_e4m3x2(fmaxf(C[t][j][3], 0.f), fmaxf(C[t][j][2], 0.f));
            st16(ra + 8u * j, lo);
            st16(rb + 8u * j, hi);
        }
    }
}

// load A fragments for m-tile t at rows warpbase + 16*t
__device__ __forceinline__ void load_act8(uint32_t (&A)[2][16], uint32_t actb, int warpbase, int lane) {
    const uint32_t row = (uint32_t)((lane & 7) + ((lane >> 3) & 1) * 8);
    const uint32_t col = (uint32_t)((lane >> 4) * 16);
    #pragma unroll
    for (int t = 0; t < 2; ++t) {
        uint32_t base = actb + (uint32_t)(warpbase + 16 * t) * ACT_ROW + row * ACT_ROW + col;
        #pragma unroll
        for (int kc = 0; kc < 4; ++kc)
            ldmx4(A[t][kc * 4], A[t][kc * 4 + 1], A[t][kc * 4 + 2], A[t][kc * 4 + 3],
                  base + (uint32_t)kc * 32u);
    }
}

extern "C" __global__ void __launch_bounds__(NTHREADS, 2)
se3_warp_mma_kernel(
    const float* __restrict__ positions,
    const float* __restrict__ directions,
    const float* __restrict__ warp_code,
    const float* __restrict__ br,
    const float* __restrict__ bv,
    float* __restrict__ out, int N)
{
    extern __shared__ char smc[];
    const uint32_t sb = smem_to_u32(smc);
    const int tid = threadIdx.x;
    const int lane = tid & 31;
    const int warp = tid >> 5;
    const int warpbase = warp * 32;
    const int base = blockIdx.x * TILE_M;

    float* sbias0 = (float*)(smc + SBIAS0_OFF);
    float* sbias1 = (float*)(smc + SBIAS1_OFF);
    float* scr    = (float*)(smc + SCREW_OFF);

    // ---- pre-phase: stage L0 async; encode one point per thread into fp8 enc rows ----
    stage_async(sb + WB0_OFF, g_wscratch + SLOT_OFF[0], 2560 / 4,
                g_biasg + 0 * 128, sb + SBIAS0_OFF, tid, NTHREADS);
    CP_COMMIT();
    {
        int g = base + tid; if (g >= N) g = N - 1;
        const float TWO_PI = 6.283185307179586f;
        float p0 = positions[g*3+0], p1 = positions[g*3+1], p2 = positions[g*3+2];
        float pp[3] = {p0, p1, p2};
        float vals[64];
        #pragma unroll
        for (int i = 0; i < 3; ++i) {
            float s = TWO_PI * pp[i];
            #pragma unroll
            for (int j = 0; j < 7; ++j) {
                vals[i*7 + j]      = __sinf(s);
                vals[21 + i*7 + j] = __cosf(s);
                s *= 2.0f;
            }
        }
        vals[42] = p0; vals[43] = p1; vals[44] = p2;
        #pragma unroll
        for (int q = 0; q < 8; ++q) vals[45 + q] = warp_code[g*8 + q];
        #pragma unroll
        for (int q = 53; q < 64; ++q) vals[q] = 0.0f;

        uint32_t* erow = (uint32_t*)(smc + ENC_OFF + tid * ENC_ROW);
        #pragma unroll
        for (int w = 0; w < 16; ++w)
            erow[w] = pack4_fp8(vals[4*w], vals[4*w+1], vals[4*w+2], vals[4*w+3]);
    }
    CP_WAIT_ALL();
    __syncthreads();

    // ---- enc A fragments (2 k32-chunks x 2 m-tiles at rows warpbase+16*t; live through L4) ----
    uint32_t Aenc[2][8];
    {
        const uint32_t row = (uint32_t)((lane & 7) + ((lane >> 3) & 1) * 8);
        const uint32_t col = (uint32_t)((lane >> 4) * 16);
        #pragma unroll
        for (int t = 0; t < 2; ++t) {
            uint32_t eb = sb + ENC_OFF + (uint32_t)(warpbase + 16 * t) * ENC_ROW + row * ENC_ROW + col;
            #pragma unroll
            for (int kc = 0; kc < 2; ++kc)
                ldmx4(Aenc[t][kc*4], Aenc[t][kc*4+1], Aenc[t][kc*4+2], Aenc[t][kc*4+3],
                      eb + (uint32_t)kc * 32u);
        }
    }

    float C[2][16][4];
    uint32_t Aact[2][16];

    // phase 0: stage L1 -> WB1 ; compute L0 (WB0, 80B rows, enc only)
    stage_async(sb + WB1_OFF, g_wscratch + SLOT_OFF[1], 4608 / 4, g_biasg + 128, sb + SBIAS1_OFF, tid, NTHREADS);
    CP_COMMIT();
    do_layer8<2, 2, WROW_L0>(C, Aenc, Aact, sb + WB0_OFF, sbias0, lane);
    store_act8(C, sb + ACT_OFF, warpbase, lane);
    CP_WAIT_ALL();
    __syncthreads();
    load_act8(Aact, sb + ACT_OFF, warpbase, lane);

    // phase 1: stage L2 -> WB0 ; compute L1 (WB1, 144)
    stage_async(sb + WB0_OFF, g_wscratch + SLOT_OFF[2], 4608 / 4, g_biasg + 256, sb + SBIAS0_OFF, tid, NTHREADS);
    CP_COMMIT();
    do_layer8<4, 0, WROW_MID>(C, Aenc, Aact, sb + WB1_OFF, sbias1, lane);
    store_act8(C, sb + ACT_OFF, warpbase, lane);
    CP_WAIT_ALL();
    __syncthreads();
    load_act8(Aact, sb + ACT_OFF, warpbase, lane);

    // phase 2: stage L3 -> WB1 ; compute L2 (WB0, 144)
    stage_async(sb + WB1_OFF, g_wscratch + SLOT_OFF[3], 4608 / 4, g_biasg + 384, sb + SBIAS1_OFF, tid, NTHREADS);
    CP_COMMIT();
    do_layer8<4, 0, WROW_MID>(C, Aenc, Aact, sb + WB0_OFF, sbias0, lane);
    store_act8(C, sb + ACT_OFF, warpbase, lane);
    CP_WAIT_ALL();
    __syncthreads();
    load_act8(Aact, sb + ACT_OFF, warpbase, lane);

    // phase 3: stage L4 -> WB0 ; compute L3 (WB1, 144)
    stage_async(sb + WB0_OFF, g_wscratch + SLOT_OFF[4], 6656 / 4, g_biasg + 512, sb + SBIAS0_OFF, tid, NTHREADS);
    CP_COMMIT();
    do_layer8<4, 0, WROW_MID>(C, Aenc, Aact, sb + WB1_OFF, sbias1, lane);
    store_act8(C, sb + ACT_OFF, warpbase, lane);
    CP_WAIT_ALL();
    __syncthreads();
    load_act8(Aact, sb + ACT_OFF, warpbase, lane);

    // phase 4: stage L5 -> WB1 ; compute L4 (WB0, 208, K = 2 enc + 4 act chunks)
    stage_async(sb + WB1_OFF, g_wscratch + SLOT_OFF[5], 4608 / 4, g_biasg + 640, sb + SBIAS1_OFF, tid, NTHREADS);
    CP_COMMIT();
    do_layer8<6, 2, WROW_L4>(C, Aenc, Aact, sb + WB0_OFF, sbias0, lane);
    store_act8(C, sb + ACT_OFF, warpbase, lane);
    CP_WAIT_ALL();
    __syncthreads();
    load_act8(Aact, sb + ACT_OFF, warpbase, lane);

    // phase 5: stage head -> WB0 ; compute L5 (WB1, 144)
    stage_async(sb + WB0_OFF, g_wscratch + SLOT_OFF[6], 288 / 4, nullptr, 0, tid, NTHREADS);
    CP_COMMIT();
    do_layer8<4, 0, WROW_MID>(C, Aenc, Aact, sb + WB1_OFF, sbias1, lane);
    store_act8(C, sb + ACT_OFF, warpbase, lane);
    CP_WAIT_ALL();
    __syncthreads();
    load_act8(Aact, sb + ACT_OFF, warpbase, lane);

    // ---- head MMA (f32 accum, weights pre-scaled x4096) ----
    {
        float hc[2][4] = {{0.f,0.f,0.f,0.f},{0.f,0.f,0.f,0.f}};
        const uint32_t hb = sb + WB0_OFF + (uint32_t)(lane & 7) * WROW_MID
                          + (uint32_t)((lane >> 3) & 1) * 16u;
        #pragma unroll
        for (int kc = 0; kc < 4; ++kc) {
            uint32_t r0, r1;
            ldmx2(r0, r1, hb + (uint32_t)kc * 32u);
            mma8(hc[0], &Aact[0][kc * 4], r0, r1);
            mma8(hc[1], &Aact[1][kc * 4], r0, r1);
        }
        int n0 = (lane & 3) * 2;
        #pragma unroll
        for (int t = 0; t < 2; ++t) {
            int m0 = warpbase + t * 16 + (lane >> 2);
            scr[m0 * 8 + n0]           = hc[t][0] * HEAD_INV;
            scr[m0 * 8 + n0 + 1]       = hc[t][1] * HEAD_INV;
            scr[(m0 + 8) * 8 + n0]     = hc[t][2] * HEAD_INV;
            scr[(m0 + 8) * 8 + n0 + 1] = hc[t][3] * HEAD_INV;
        }
    }
    __syncthreads();

    // ---- SE(3) exp-map epilogue: one thread per point ----
    {
        const int p = tid;
        const int g = base + p;
        if (g < N) {
            float vx = scr[p*8+0] + __ldg(bv + 0);
            float vy = scr[p*8+1] + __ldg(bv + 1);
            float vz = scr[p*8+2] + __ldg(bv + 2);
            float wx = scr[p*8+3] + __ldg(br + 0);
            float wy = scr[p*8+4] + __ldg(br + 1);
            float wz = scr[p*8+5] + __ldg(br + 2);

            float ang2 = fmaxf(wx*wx + wy*wy + wz*wz, 1e-4f);
            float ang  = sqrtf(ang2);
            float sa = sinf(ang), ca = cosf(ang);
            float f1 = sa / ang;
            float f2 = (1.0f - ca) / ang2;
            float f3 = (ang - sa) / (ang * ang2);

            float K[3][3] = {{0.f,  wz, -wy},
                             {-wz, 0.f,  wx},
                             { wy, -wx, 0.f}};
            float KK[3][3];
            #pragma unroll
            for (int a = 0; a < 3; ++a)
                #pragma unroll
                for (int b = 0; b < 3; ++b)
                    KK[a][b] = K[a][0]*K[0][b] + K[a][1]*K[1][b] + K[a][2]*K[2][b];

            float R[3][3], V[3][3];
            #pragma unroll
            for (int a = 0; a < 3; ++a)
                #pragma unroll
                for (int b = 0; b < 3; ++b) {
                    float I = (a == b) ? 1.0f : 0.0f;
                    R[a][b] = I + f1*K[a][b] + f2*KK[a][b];
                    V[a][b] = I + f2*K[a][b] + f3*KK[a][b];
                }
            float T0 = V[0][0]*vx + V[0][1]*vy + V[0][2]*vz;
            float T1 = V[1][0]*vx + V[1][1]*vy + V[1][2]*vz;
            float T2 = V[2][0]*vx + V[2][1]*vy + V[2][2]*vz;

            float px = positions[g*3+0],  py = positions[g*3+1],  pz = positions[g*3+2];
            float dx = directions[g*3+0], dy = directions[g*3+1], dz = directions[g*3+2];

            // M[:3,:3] = R^T, M[:3,3] = T  =>  wp = R^T p + T, wd = R^T d
            float wp0 = R[0][0]*px + R[1][0]*py + R[2][0]*pz + T0;
            float wp1 = R[0][1]*px + R[1][1]*py + R[2][1]*pz + T1;
            float wp2 = R[0][2]*px + R[1][2]*py + R[2][2]*pz + T2;
            float wd0 = R[0][0]*dx + R[1][0]*dy + R[2][0]*dz;
            float wd1 = R[0][1]*dx + R[1][1]*dy + R[2][1]*dz;
            float wd2 = R[0][2]*dx + R[1][2]*dy + R[2][2]*dz;

            wp0 = isnan(wp0) ? px : wp0;
            wp1 = isnan(wp1) ? py : wp1;
            wp2 = isnan(wp2) ? pz : wp2;
            wd0 = isnan(wd0) ? dx : wd0;
            wd1 = isnan(wd1) ? dy : wd1;
            wd2 = isnan(wd2) ? dz : wd2;

            out[g*3+0] = wp0; out[g*3+1] = wp1; out[g*3+2] = wp2;
            long long off = 3LL * N;
            out[off + g*3+0] = wd0; out[off + g*3+1] = wd1; out[off + g*3+2] = wd2;
        }
    }
}

// ============================ launch ============================
extern "C" void kernel_launch(void* const* d_in, const int* in_sizes, int n_in,
                              void* d_out, int out_size) {
    const float* positions  = (const float*)d_in[0];
    const float* directions = (const float*)d_in[1];
    const float* warp_code  = (const float*)d_in[2];
    const float* W0 = (const float*)d_in[3];  const float* b0 = (const float*)d_in[4];
    const float* W1 = (const float*)d_in[5];  const float* b1 = (const float*)d_in[6];
    const float* W2 = (const float*)d_in[7];  const float* b2 = (const float*)d_in[8];
    const float* W3 = (const float*)d_in[9];  const float* b3 = (const float*)d_in[10];
    const float* W4 = (const float*)d_in[11]; const float* b4 = (const float*)d_in[12];
    const float* W5 = (const float*)d_in[13]; const float* b5 = (const float*)d_in[14];
    const float* Wr = (const float*)d_in[15]; const float* br = (const float*)d_in[16];
    const float* Wv = (const float*)d_in[17]; const float* bv = (const float*)d_in[18];

    int N = in_sizes[0] / 3;
    int blocks = (N + TILE_M - 1) / TILE_M;

    dim3 pgrid(27, 7);
    prep_weights<<<pgrid, 256>>>(W0, W1, W2, W3, W4, W5, Wv, Wr,
                                 b0, b1, b2, b3, b4, b5);

    cudaFuncSetAttribute(se3_warp_mma_kernel,
                         cudaFuncAttributeMaxDynamicSharedMemorySize, SMEM_BYTES);
    se3_warp_mma_kernel<<<blocks, NTHREADS, SMEM_BYTES>>>(
        positions, directions, warp_code, br, bv, (float*)d_out, N);
}

// round 15
// speedup vs baseline: 2.0054x; 2.0054x over previous
#include <cuda_runtime.h>
#include <cuda_fp16.h>
#include <cstdint>
#include <math.h>

// ============================ config ============================
#define NTHREADS 128
#define TILE_M   128          // 4 warps x m=32, 3 CTAs/SM

// f16 row strides (bytes); stride/4 mod 32 == 4 -> conflict-free ldmatrix
#define WROW0_B  144          // K=64  (L0, L4a)
#define WROW1_B  272          // K=128 (L1,L2,L3,L4b,L5,head)
#define ENC_ROW_B 144

// g_wscratch word offsets per slot {L0,L1,L2,L3,L4a,L4b,L5,head}
__device__ __constant__ int SLOT_OFF[8] = {0, 4608, 13312, 22016, 30720, 35328, 44032, 52736};
__device__ uint32_t g_wscratch[53280];
__device__ float    g_biasg[6 * 128];

// smem layout (bytes): two 34816B weight/enc buffers + bias + screw
#define BUF_A      0
#define BUF_B      34816
#define SBIAS0_OFF 69632
#define SBIAS1_OFF 70144
#define SCREW_OFF  70656      // 128 x 8 f32
#define SMEM_BYTES 74752      // x3 CTAs = 224256 <= 228KB/SM

// ============================ helpers ============================
__device__ __forceinline__ uint32_t smem_to_u32(const void* p) {
    uint32_t a;
    asm("{ .reg .u64 t; cvta.to.shared.u64 t, %1; cvt.u32.u64 %0, t; }" : "=r"(a) : "l"(p));
    return a;
}

__device__ __forceinline__ void ldmx4(uint32_t& r0, uint32_t& r1, uint32_t& r2, uint32_t& r3, uint32_t addr) {
    asm volatile("ldmatrix.sync.aligned.m8n8.x4.shared.b16 {%0,%1,%2,%3}, [%4];"
        : "=r"(r0), "=r"(r1), "=r"(r2), "=r"(r3) : "r"(addr));
}

// f16 inputs, f16 accumulators (C packed f16x2)
__device__ __forceinline__ void mma_h(uint32_t (&c)[2],
    uint32_t a0, uint32_t a1, uint32_t a2, uint32_t a3, uint32_t b0, uint32_t b1) {
    asm volatile("mma.sync.aligned.m16n8k16.row.col.f16.f16.f16.f16 "
        "{%0,%1}, {%2,%3,%4,%5}, {%6,%7}, {%0,%1};"
        : "+r"(c[0]), "+r"(c[1])
        : "r"(a0), "r"(a1), "r"(a2), "r"(a3), "r"(b0), "r"(b1));
}

// f16 inputs, f32 accumulators (head)
__device__ __forceinline__ void mma_hf32(float (&c)[4],
    uint32_t a0, uint32_t a1, uint32_t a2, uint32_t a3, uint32_t b0, uint32_t b1) {
    asm volatile("mma.sync.aligned.m16n8k16.row.col.f32.f16.f16.f32 "
        "{%0,%1,%2,%3}, {%4,%5,%6,%7}, {%8,%9}, {%0,%1,%2,%3};"
        : "+f"(c[0]), "+f"(c[1]), "+f"(c[2]), "+f"(c[3])
        : "r"(a0), "r"(a1), "r"(a2), "r"(a3), "r"(b0), "r"(b1));
}

__device__ __forceinline__ uint32_t pack_h2(float lo, float hi) {
    __half2 h = __floats2half2_rn(lo, hi);
    return *reinterpret_cast<uint32_t*>(&h);
}

__device__ __forceinline__ uint32_t relu_h2(uint32_t x) {
    __half2 h = *reinterpret_cast<__half2*>(&x);
    h = __hmax2(h, __float2half2_rn(0.0f));
    return *reinterpret_cast<uint32_t*>(&h);
}

__device__ __forceinline__ void cp_async16(uint32_t dst, const void* src) {
    asm volatile("cp.async.cg.shared.global [%0], [%1], 16;" :: "r"(dst), "l"(src));
}
#define CP_COMMIT()   asm volatile("cp.async.commit_group;" ::: "memory")
#define CP_WAIT_ALL() asm volatile("cp.async.wait_all;" ::: "memory")

// weight element fetch (k = element index)
// mode 0: fan_in 128 | 1: L0 53->pad64 | 2: L4a enc half (53->pad64) | 3: L4b act half | 4: head
__device__ __forceinline__ float wfetch(int mode, int n, int k, const float* Wa, const float* Wb) {
    if (mode == 0) return __ldg(Wa + n * 128 + k);
    if (mode == 1) return (k < 53) ? __ldg(Wa + n * 53 + k) : 0.0f;
    if (mode == 2) return (k < 53) ? __ldg(Wa + n * 181 + k) : 0.0f;
    if (mode == 3) return __ldg(Wa + n * 181 + 53 + k);
    // mode 4: head rows = [Wv0..2, Wr0..2, 0, 0]
    if (n < 3) return __ldg(Wa + n * 128 + k);
    if (n < 6) return __ldg(Wb + (n - 3) * 128 + k);
    return 0.0f;
}

// ============================ prep kernel ============================
__global__ void prep_weights(
    const float* W0, const float* W1, const float* W2, const float* W3,
    const float* W4, const float* W5, const float* Wv, const float* Wr,
    const float* b0, const float* b1, const float* b2, const float* b3,
    const float* b4, const float* b5)
{
    int slot = blockIdx.y;
    int idx = blockIdx.x * 256 + threadIdx.x;
    uint32_t* dst = g_wscratch + SLOT_OFF[slot];

    const float *Wa = nullptr, *Wb = nullptr, *bb = nullptr;
    int mode = 0, rows = 128, wroww = 68, datw = 64, bidx = -1;
    switch (slot) {
        case 0: Wa = W0; mode = 1; wroww = 36; datw = 32; bb = b0; bidx = 0; break;
        case 1: Wa = W1; mode = 0; wroww = 68; datw = 64; bb = b1; bidx = 1; break;
        case 2: Wa = W2; mode = 0; wroww = 68; datw = 64; bb = b2; bidx = 2; break;
        case 3: Wa = W3; mode = 0; wroww = 68; datw = 64; bb = b3; bidx = 3; break;
        case 4: Wa = W4; mode = 2; wroww = 36; datw = 32; bb = b4; bidx = 4; break;  // L4a
        case 5: Wa = W4; mode = 3; wroww = 68; datw = 64; break;                     // L4b
        case 6: Wa = W5; mode = 0; wroww = 68; datw = 64; bb = b5; bidx = 5; break;
        case 7: Wa = Wv; Wb = Wr; mode = 4; rows = 8; wroww = 68; datw = 64; break;  // head
    }
    int words = rows * wroww;
    if (idx < words) {
        int n = idx / wroww;
        int kpos = idx - n * wroww;
        float f0 = 0.0f, f1 = 0.0f;
        if (kpos < datw) {
            int k = kpos * 2;
            f0 = wfetch(mode, n, k,     Wa, Wb);
            f1 = wfetch(mode, n, k + 1, Wa, Wb);
        }
        dst[idx] = pack_h2(f0, f1);
    } else if (bb && (idx - words) < 128) {
        g_biasg[bidx * 128 + (idx - words)] = __ldg(bb + (idx - words));
    }
}

// ============================ main kernel pieces ============================
__device__ __forceinline__ void stage_async(uint32_t dst, const uint32_t* src, int words4,
                                            const float* bsrc, uint32_t sbias_dst, int t, int nthr) {
    const uint4* s = (const uint4*)src;
    #pragma unroll 4
    for (int i = t; i < words4; i += nthr)
        cp_async16(dst + (uint32_t)i * 16u, s + i);
    if (bsrc && t < 32)
        cp_async16(sbias_dst + (uint32_t)t * 16u, (const uint4*)bsrc + t);
}

// one dense layer, kc-outer / nt-inner; INIT=false continues accumulation (L4 split)
template<int NCH, int ENCCH, int WROWB, bool INIT>
__device__ __forceinline__ void do_layer(uint32_t (&C)[2][16][2],
    const uint32_t (&Aenc)[2][16], const uint32_t (&Aact)[2][32],
    uint32_t wbase, const float* sbias, int lane)
{
    if (INIT) {
        const int nb = (lane & 3) * 2;
        #pragma unroll
        for (int nt = 0; nt < 16; ++nt) {
            uint32_t bp = pack_h2(sbias[nt * 8 + nb], sbias[nt * 8 + nb + 1]);
            C[0][nt][0] = bp; C[0][nt][1] = bp;
            C[1][nt][0] = bp; C[1][nt][1] = bp;
        }
    }
    const uint32_t baddr = wbase + (uint32_t)(lane & 7) * WROWB + (uint32_t)(lane >> 3) * 16u;
    #pragma unroll
    for (int kc = 0; kc < NCH; kc += 2) {
        const uint32_t* A00 = (kc     < ENCCH) ? &Aenc[0][kc * 4]       : &Aact[0][(kc - ENCCH) * 4];
        const uint32_t* A01 = (kc     < ENCCH) ? &Aenc[1][kc * 4]       : &Aact[1][(kc - ENCCH) * 4];
        const uint32_t* A10 = (kc + 1 < ENCCH) ? &Aenc[0][(kc + 1) * 4] : &Aact[0][(kc + 1 - ENCCH) * 4];
        const uint32_t* A11 = (kc + 1 < ENCCH) ? &Aenc[1][(kc + 1) * 4] : &Aact[1][(kc + 1 - ENCCH) * 4];
        const uint32_t kaddr = baddr + (uint32_t)kc * 32u;
        #pragma unroll
        for (int nt = 0; nt < 16; ++nt) {
            uint32_t b0, b1, b2, b3;
            ldmx4(b0, b1, b2, b3, kaddr + (uint32_t)nt * (8u * WROWB));
            mma_h(C[0][nt], A00[0], A00[1], A00[2], A00[3], b0, b1);
            mma_h(C[1][nt], A01[0], A01[1], A01[2], A01[3], b0, b1);
            mma_h(C[0][nt], A10[0], A10[1], A10[2], A10[3], b2, b3);
            mma_h(C[1][nt], A11[0], A11[1], A11[2], A11[3], b2, b3);
        }
    }
}

// relu; C f16x2 fragments map 1:1 onto next layer's A fragments
__device__ __forceinline__ void repack(const uint32_t (&C)[2][16][2], uint32_t (&A)[2][32]) {
    #pragma unroll
    for (int t = 0; t < 2; ++t)
        #pragma unroll
        for (int j = 0; j < 8; ++j) {
            A[t][j*4+0] = relu_h2(C[t][2*j][0]);
            A[t][j*4+1] = relu_h2(C[t][2*j][1]);
            A[t][j*4+2] = relu_h2(C[t][2*j+1][0]);
            A[t][j*4+3] = relu_h2(C[t][2*j+1][1]);
        }
}

extern "C" __global__ void __launch_bounds__(NTHREADS, 3)
se3_warp_mma_kernel(
    const float* __restrict__ positions,
    const float* __restrict__ directions,
    const float* __restrict__ warp_code,
    const float* __restrict__ br,
    const float* __restrict__ bv,
    float* __restrict__ out, int N)
{
    extern __shared__ char smc[];
    const uint32_t sb = smem_to_u32(smc);
    const int tid = threadIdx.x;
    const int lane = tid & 31;
    const int warp = tid >> 5;
    const int warpbase = warp * 32;
    const int base = blockIdx.x * TILE_M;

    float* sbias0 = (float*)(smc + SBIAS0_OFF);
    float* sbias1 = (float*)(smc + SBIAS1_OFF);
    float* scr    = (float*)(smc + SCREW_OFF);

    const uint32_t bufA = sb + BUF_A;
    const uint32_t bufB = sb + BUF_B;

    // ---- pre-phase: stage L0 -> B (async); encode one point per thread into A ----
    stage_async(bufB, g_wscratch + SLOT_OFF[0], 4608 / 4,
                g_biasg + 0 * 128, sb + SBIAS0_OFF, tid, NTHREADS);
    CP_COMMIT();
    {
        int g = base + tid; if (g >= N) g = N - 1;
        const float TWO_PI = 6.283185307179586f;
        float p0 = positions[g*3+0], p1 = positions[g*3+1], p2 = positions[g*3+2];
        float pp[3] = {p0, p1, p2};
        float vals[64];
        #pragma unroll
        for (int i = 0; i < 3; ++i) {
            float s = TWO_PI * pp[i];
            #pragma unroll
            for (int j = 0; j < 7; ++j) {
                vals[i*7 + j]      = __sinf(s);
                vals[21 + i*7 + j] = __cosf(s);
                s *= 2.0f;
            }
        }
        vals[42] = p0; vals[43] = p1; vals[44] = p2;
        #pragma unroll
        for (int q = 0; q < 8; ++q) vals[45 + q] = warp_code[g*8 + q];
        #pragma unroll
        for (int q = 53; q < 64; ++q) vals[q] = 0.0f;

        char* erow = smc + BUF_A + tid * ENC_ROW_B;
        #pragma unroll
        for (int j = 0; j < 32; ++j)
            *(uint32_t*)(erow + j * 4) = pack_h2(vals[2*j], vals[2*j + 1]);
    }
    __syncwarp();   // enc rows for this warp's Aenc are warp-private (rows == tids of this warp)

    // ---- load enc A fragments from A BEFORE barrier (phase0 staging overwrites A) ----
    uint32_t Aenc[2][16];
    {
        const int tileid = lane >> 3;
        const uint32_t arow_off = (uint32_t)((lane & 7) + (tileid & 1) * 8);
        const uint32_t acol = (uint32_t)((tileid >> 1) * 16);
        #pragma unroll
        for (int t = 0; t < 2; ++t) {
            uint32_t abase = bufA + (uint32_t)(warpbase + t * 16) * ENC_ROW_B
                           + arow_off * ENC_ROW_B + acol;
            #pragma unroll
            for (int ch = 0; ch < 4; ++ch)
                ldmx4(Aenc[t][ch*4+0], Aenc[t][ch*4+1], Aenc[t][ch*4+2], Aenc[t][ch*4+3],
                      abase + (uint32_t)ch * 32u);
        }
    }
    CP_WAIT_ALL();
    __syncthreads();

    uint32_t C[2][16][2];
    uint32_t Aact[2][32];

    // phase 0: stage L1 -> A (overwrites enc; Aenc already in regs) ; compute L0 (B, 144B rows)
    stage_async(bufA, g_wscratch + SLOT_OFF[1], 8704 / 4, g_biasg + 128, sb + SBIAS1_OFF, tid, NTHREADS);
    CP_COMMIT();
    do_layer<4, 4, WROW0_B, true>(C, Aenc, Aact, bufB, sbias0, lane);
    repack(C, Aact);
    CP_WAIT_ALL();
    __syncthreads();

    // phase 1: stage L2 -> B ; compute L1 (A, 272)
    stage_async(bufB, g_wscratch + SLOT_OFF[2], 8704 / 4, g_biasg + 256, sb + SBIAS0_OFF, tid, NTHREADS);
    CP_COMMIT();
    do_layer<8, 0, WROW1_B, true>(C, Aenc, Aact, bufA, sbias1, lane);
    repack(C, Aact);
    CP_WAIT_ALL();
    __syncthreads();

    // phase 2: stage L3 -> A ; compute L2 (B, 272)
    stage_async(bufA, g_wscratch + SLOT_OFF[3], 8704 / 4, g_biasg + 384, sb + SBIAS1_OFF, tid, NTHREADS);
    CP_COMMIT();
    do_layer<8, 0, WROW1_B, true>(C, Aenc, Aact, bufB, sbias0, lane);
    repack(C, Aact);
    CP_WAIT_ALL();
    __syncthreads();

    // phase 3: stage L4a -> B (enc half, 144B rows) ; compute L3 (A, 272)
    stage_async(bufB, g_wscratch + SLOT_OFF[4], 4608 / 4, g_biasg + 512, sb + SBIAS0_OFF, tid, NTHREADS);
    CP_COMMIT();
    do_layer<8, 0, WROW1_B, true>(C, Aenc, Aact, bufA, sbias1, lane);
    repack(C, Aact);
    CP_WAIT_ALL();
    __syncthreads();

    // phase 4a: stage L4b -> A (act half) ; compute L4 enc-part (B, 144B rows) with bias init
    stage_async(bufA, g_wscratch + SLOT_OFF[5], 8704 / 4, nullptr, 0, tid, NTHREADS);
    CP_COMMIT();
    do_layer<4, 4, WROW0_B, true>(C, Aenc, Aact, bufB, sbias0, lane);
    CP_WAIT_ALL();
    __syncthreads();

    // phase 4b: stage L5 -> B ; compute L4 act-part (A, 272), continuing accumulation
    stage_async(bufB, g_wscratch + SLOT_OFF[6], 8704 / 4, g_biasg + 640, sb + SBIAS1_OFF, tid, NTHREADS);
    CP_COMMIT();
    do_layer<8, 0, WROW1_B, false>(C, Aenc, Aact, bufA, sbias0, lane);
    repack(C, Aact);
    CP_WAIT_ALL();
    __syncthreads();

    // phase 5: stage head -> A ; compute L5 (B, 272)
    stage_async(bufA, g_wscratch + SLOT_OFF[7], 544 / 4, nullptr, 0, tid, NTHREADS);
    CP_COMMIT();
    do_layer<8, 0, WROW1_B, true>(C, Aenc, Aact, bufB, sbias1, lane);
    repack(C, Aact);
    CP_WAIT_ALL();
    __syncthreads();

    // ---- head MMA (f32 accum): screw_pre[32m x 8n] per warp, weights in A ----
    {
        float hc[2][4] = {{0.f,0.f,0.f,0.f},{0.f,0.f,0.f,0.f}};
        const uint32_t baddr = bufA + (uint32_t)(lane & 7) * WROW1_B + (uint32_t)(lane >> 3) * 16u;
        #pragma unroll
        for (int kc = 0; kc < 8; kc += 2) {
            uint32_t b0, b1, b2, b3;
            ldmx4(b0, b1, b2, b3, baddr + (uint32_t)kc * 32u);
            #pragma unroll
            for (int t = 0; t < 2; ++t) {
                mma_hf32(hc[t], Aact[t][kc*4+0], Aact[t][kc*4+1], Aact[t][kc*4+2], Aact[t][kc*4+3], b0, b1);
                mma_hf32(hc[t], Aact[t][(kc+1)*4+0], Aact[t][(kc+1)*4+1], Aact[t][(kc+1)*4+2], Aact[t][(kc+1)*4+3], b2, b3);
            }
        }
        int n0 = (lane & 3) * 2;
        #pragma unroll
        for (int t = 0; t < 2; ++t) {
            int m0 = warpbase + t * 16 + (lane >> 2);
            scr[m0 * 8 + n0]           = hc[t][0];
            scr[m0 * 8 + n0 + 1]       = hc[t][1];
            scr[(m0 + 8) * 8 + n0]     = hc[t][2];
            scr[(m0 + 8) * 8 + n0 + 1] = hc[t][3];
        }
    }
    __syncthreads();

    // ---- SE(3) exp-map epilogue: one thread per point ----
    {
        const int p = tid;
        const int g = base + p;
        if (g < N) {
            float vx = scr[p*8+0] + __ldg(bv + 0);
            float vy = scr[p*8+1] + __ldg(bv + 1);
            float vz = scr[p*8+2] + __ldg(bv + 2);
            float wx = scr[p*8+3] + __ldg(br + 0);
            float wy = scr[p*8+4] + __ldg(br + 1);
            float wz = scr[p*8+5] + __ldg(br + 2);

            float ang2 = fmaxf(wx*wx + wy*wy + wz*wz, 1e-4f);
            float ang  = sqrtf(ang2);
            float sa = sinf(ang), ca = cosf(ang);
            float f1 = sa / ang;
            float f2 = (1.0f - ca) / ang2;
            float f3 = (ang - sa) / (ang * ang2);

            float K[3][3] = {{0.f,  wz, -wy},
                             {-wz, 0.f,  wx},
                             { wy, -wx, 0.f}};
            float KK[3][3];
            #pragma unroll
            for (int a = 0; a < 3; ++a)
                #pragma unroll
                for (int b = 0; b < 3; ++b)
                    KK[a][b] = K[a][0]*K[0][b] + K[a][1]*K[1][b] + K[a][2]*K[2][b];

            float R[3][3], V[3][3];
            #pragma unroll
            for (int a = 0; a < 3; ++a)
                #pragma unroll
                for (int b = 0; b < 3; ++b) {
                    float I = (a == b) ? 1.0f : 0.0f;
                    R[a][b] = I + f1*K[a][b] + f2*KK[a][b];
                    V[a][b] = I + f2*K[a][b] + f3*KK[a][b];
                }
            float T0 = V[0][0]*vx + V[0][1]*vy + V[0][2]*vz;
            float T1 = V[1][0]*vx + V[1][1]*vy + V[1][2]*vz;
            float T2 = V[2][0]*vx + V[2][1]*vy + V[2][2]*vz;

            float px = positions[g*3+0],  py = positions[g*3+1],  pz = positions[g*3+2];
            float dx = directions[g*3+0], dy = directions[g*3+1], dz = directions[g*3+2];

            // M[:3,:3] = R^T, M[:3,3] = T  =>  wp = R^T p + T, wd = R^T d
            float wp0 = R[0][0]*px + R[1][0]*py + R[2][0]*pz + T0;
            float wp1 = R[0][1]*px + R[1][1]*py + R[2][1]*pz + T1;
            float wp2 = R[0][2]*px + R[1][2]*py + R[2][2]*pz + T2;
            float wd0 = R[0][0]*dx + R[1][0]*dy + R[2][0]*dz;
            float wd1 = R[0][1]*dx + R[1][1]*dy + R[2][1]*dz;
            float wd2 = R[0][2]*dx + R[1][2]*dy + R[2][2]*dz;

            wp0 = isnan(wp0) ? px : wp0;
            wp1 = isnan(wp1) ? py : wp1;
            wp2 = isnan(wp2) ? pz : wp2;
            wd0 = isnan(wd0) ? dx : wd0;
            wd1 = isnan(wd1) ? dy : wd1;
            wd2 = isnan(wd2) ? dz : wd2;

            out[g*3+0] = wp0; out[g*3+1] = wp1; out[g*3+2] = wp2;
            long long off = 3LL * N;
            out[off + g*3+0] = wd0; out[off + g*3+1] = wd1; out[off + g*3+2] = wd2;
        }
    }
}

// ============================ launch ============================
extern "C" void kernel_launch(void* const* d_in, const int* in_sizes, int n_in,
                              void* d_out, int out_size) {
    const float* positions  = (const float*)d_in[0];
    const float* directions = (const float*)d_in[1];
    const float* warp_code  = (const float*)d_in[2];
    const float* W0 = (const float*)d_in[3];  const float* b0 = (const float*)d_in[4];
    const float* W1 = (const float*)d_in[5];  const float* b1 = (const float*)d_in[6];
    const float* W2 = (const float*)d_in[7];  const float* b2 = (const float*)d_in[8];
    const float* W3 = (const float*)d_in[9];  const float* b3 = (const float*)d_in[10];
    const float* W4 = (const float*)d_in[11]; const float* b4 = (const float*)d_in[12];
    const float* W5 = (const float*)d_in[13]; const float* b5 = (const float*)d_in[14];
    const float* Wr = (const float*)d_in[15]; const float* br = (const float*)d_in[16];
    const float* Wv = (const float*)d_in[17]; const float* bv = (const float*)d_in[18];

    int N = in_sizes[0] / 3;
    int blocks = (N + TILE_M - 1) / TILE_M;

    dim3 pgrid(35, 8);
    prep_weights<<<pgrid, 256>>>(W0, W1, W2, W3, W4, W5, Wv, Wr,
                                 b0, b1, b2, b3, b4, b5);

    cudaFuncSetAttribute(se3_warp_mma_kernel,
                         cudaFuncAttributeMaxDynamicSharedMemorySize, SMEM_BYTES);
    se3_warp_mma_kernel<<<blocks, NTHREADS, SMEM_BYTES>>>(
        positions, directions, warp_code, br, bv, (float*)d_out, N);
}